// round 16
// baseline (speedup 1.0000x reference)
#include <cuda_runtime.h>
#include <cstdint>

#define DDIM 64
#define KCODES 1024
#define NTOK 131072
#define TM 64
#define NTHREADS 256
#define PASSES 8
#define CPASS 128

typedef unsigned long long ull;

// ---------------- smem layout (bytes) ----------------
#define OFF_XF   0                    // float [64][64] = 16384 (d-major)
#define OFF_CS   16384                // 2 x float [64][128] = 65536 (double-buffered)
#define CS_STRIDE 32768
#define OFF_CN   81920                // float [1024] = 4096
#define OFF_XNS  86016                // float [64]
#define OFF_WIX  86272                // int [64]
#define SMEM_BYTES 86528
// reduction overlays Cs after the last pass:
#define OFF_REDV OFF_CS               // float [8][64] = 2048
#define OFF_REDI (OFF_CS + 2048)      // int   [8][64] = 2048

__device__ float g_cn[KCODES];                        // ||c||^2 (sequential, ref order)
__device__ __align__(16) float g_cbT[DDIM * KCODES];  // transposed codebook [d][k]

__global__ void vq_prep(const float* __restrict__ cb) {
    int k = blockIdx.x * blockDim.x + threadIdx.x;
    if (k >= KCODES) return;
    float acc = 0.f;
#pragma unroll
    for (int d = 0; d < DDIM; d++) {
        float c = cb[k * DDIM + d];
        acc = __fadd_rn(acc, __fmul_rn(c, c));
        g_cbT[d * KCODES + k] = c;
    }
    g_cn[k] = acc;
}

__device__ __forceinline__ uint32_t smem_u32(const void* p) {
    uint32_t a;
    asm("{ .reg .u64 t; cvta.to.shared.u64 t, %1; cvt.u32.u64 %0, t; }" : "=r"(a) : "l"(p));
    return a;
}
__device__ __forceinline__ void lds2f(float& a0, float& a1, uint32_t a) {
    asm volatile("ld.shared.v2.f32 {%0,%1}, [%2];" : "=f"(a0), "=f"(a1) : "r"(a));
}
__device__ __forceinline__ void lds2u64(ull& a0, ull& a1, uint32_t a) {
    asm volatile("ld.shared.v2.b64 {%0,%1}, [%2];" : "=l"(a0), "=l"(a1) : "r"(a));
}
__device__ __forceinline__ ull rep2f(float x) {
    ull r;
    asm("{ .reg .b32 t; mov.b32 t, %1; mov.b64 %0, {t,t}; }" : "=l"(r) : "f"(x));
    return r;
}
__device__ __forceinline__ void fma2(ull& acc, ull x, ull c) {
    asm("fma.rn.f32x2 %0, %1, %2, %0;" : "+l"(acc) : "l"(x), "l"(c));
}

// async-fill one pass's code tile: Cs[buf][d][128] <- g_cbT[d][p*128 + col]
__device__ __forceinline__ void issue_cs(uint32_t sbase, int buf, int p) {
#pragma unroll
    for (int k = 0; k < 8; k++) {
        int i = threadIdx.x + k * NTHREADS;          // uint4 slot 0..2047
        int d = i >> 5;
        int col = (i & 31) << 2;
        uint32_t dst = sbase + OFF_CS + buf * CS_STRIDE + (uint32_t)((d * 128 + col) * 4);
        const char* src = (const char*)(g_cbT + d * KCODES + p * CPASS + col);
        asm volatile("cp.async.ca.shared.global [%0], [%1], 16;"
                     :: "r"(dst), "l"(src) : "memory");
    }
    asm volatile("cp.async.commit_group;" ::: "memory");
}

__global__ __launch_bounds__(NTHREADS, 2)
void vq_main(const float* __restrict__ h, const float* __restrict__ cb,
             float* __restrict__ outZ, float* __restrict__ outQ) {
    extern __shared__ char smem[];
    float* Xf  = (float*)(smem + OFF_XF);    // [64][64] d-major
    float* Cn  = (float*)(smem + OFF_CN);
    float* xns = (float*)(smem + OFF_XNS);
    int*   wix = (int*)(smem + OFF_WIX);
    float* redv = (float*)(smem + OFF_REDV);
    int*   redi = (int*)(smem + OFF_REDI);
    const uint32_t sbase = smem_u32(smem);

    const int tid = threadIdx.x;
    const int wid = tid >> 5;                 // 8 warps
    const int l = tid & 31;
    const int n0 = blockIdx.x * TM;
    const int b = n0 >> 12;
    const long base = (long)b * 262144 + (n0 & 4095);   // 4096 % 64 == 0: no batch cross

    // kick off pass-0 code tile immediately (overlaps the Xf gmem loads below)
    issue_cs(sbase, 0, 0);

    // ---- Xf [d][t]: coalesced LDG.128 -> STS.128, conflict-free ----
    for (int i = tid; i < 64 * 16; i += NTHREADS) {
        int d = i >> 4, t4 = i & 15;
        *(float4*)&Xf[d * 64 + t4 * 4] =
            *(const float4*)(h + base + (long)d * 4096 + t4 * 4);
    }
    for (int i = tid; i < KCODES; i += NTHREADS) Cn[i] = g_cn[i];
    __syncthreads();

    // ---- exact xn (sequential mul-then-add; bit-matches reference, R2-verified) ----
    if (tid < 64) {
        float acc = 0.f;
#pragma unroll
        for (int d = 0; d < 64; d++) {
            float xv = Xf[d * 64 + tid];
            acc = __fadd_rn(acc, __fmul_rn(xv, xv));
        }
        xns[tid] = acc;
    }
    __syncthreads();

    // lane l owns tokens 2l, 2l+1; warp w owns 16 codes per pass
    float xn0 = xns[2 * l], xn1 = xns[2 * l + 1];
    float best[2] = {3.4e38f, 3.4e38f};
    int bidx[2] = {0, 0};

    const uint32_t xaddr = sbase + OFF_XF + 8u * l;   // float2 of this lane's 2 tokens

#pragma unroll 1
    for (int p = 0; p < PASSES; p++) {
        // R13-verified order: wait for buf[p&1], BARRIER (separates pass p-1 reads
        // from the upcoming overwrite), THEN issue prefetch of pass p+1.
        asm volatile("cp.async.wait_group 0;" ::: "memory");
        __syncthreads();
        if (p + 1 < PASSES) issue_cs(sbase, (p + 1) & 1, p + 1);

        const uint32_t caddr = sbase + OFF_CS + (uint32_t)((p & 1) * CS_STRIDE) + 64u * wid;

        // acc[cp][t] = {s(k=2cp), s(k=2cp+1)} (FFMA2 chain from 0 = R2-exact)
        ull acc[8][2];
#pragma unroll
        for (int cp = 0; cp < 8; cp++) { acc[cp][0] = 0ull; acc[cp][1] = 0ull; }

#pragma unroll 2
        for (int d = 0; d < 64; d++) {
            float f0, f1;
            lds2f(f0, f1, xaddr + (uint32_t)(d * 256));
            ull x0 = rep2f(f0), x1 = rep2f(f1);
            uint32_t ca = caddr + (uint32_t)(d * 512);
#pragma unroll
            for (int cq = 0; cq < 4; cq++) {
                ull c0, c1;                     // {c_k,c_k+1} natural pairs, warp-uniform
                lds2u64(c0, c1, ca + cq * 16);
                fma2(acc[cq * 2 + 0][0], x0, c0);
                fma2(acc[cq * 2 + 0][1], x1, c0);
                fma2(acc[cq * 2 + 1][0], x0, c1);
                fma2(acc[cq * 2 + 1][1], x1, c1);
            }
        }

        // epilogue: d2 = fl(fl(xn-2s)+cn), running argmin (ascending k, strict <)
        const int kw = p * CPASS + wid * 16;
#pragma unroll
        for (int cp = 0; cp < 8; cp++) {
            int k0 = kw + cp * 2;
            float cn0 = Cn[k0], cn1 = Cn[k0 + 1];
#pragma unroll
            for (int t = 0; t < 2; t++) {
                float xnv = t ? xn1 : xn0;
                ull a = acc[cp][t];
                float slo = __uint_as_float((unsigned)(a & 0xffffffffull));
                float shi = __uint_as_float((unsigned)(a >> 32));
                float d2a = __fadd_rn(__fsub_rn(xnv, 2.0f * slo), cn0);
                float d2b = __fadd_rn(__fsub_rn(xnv, 2.0f * shi), cn1);
                if (d2a < best[t]) { best[t] = d2a; bidx[t] = k0; }
                if (d2b < best[t]) { best[t] = d2b; bidx[t] = k0 + 1; }
            }
        }
    }

    // ---- cross-warp reduce (lexicographic: value, then lowest k) ----
    __syncthreads();   // all passes done; safe to overlay Cs with reduction arrays
#pragma unroll
    for (int t = 0; t < 2; t++) {
        redv[wid * 64 + 2 * l + t] = best[t];
        redi[wid * 64 + 2 * l + t] = bidx[t];
    }
    __syncthreads();

    if (tid < 64) {
        float bv = redv[tid];
        int bi = redi[tid];
#pragma unroll
        for (int w = 1; w < 8; w++) {
            float v = redv[w * 64 + tid];
            int i2 = redi[w * 64 + tid];
            if (v < bv || (v == bv && i2 < bi)) { bv = v; bi = i2; }
        }
        wix[tid] = bi;
        if (outZ) outZ[n0 + tid] = (float)bi;
    }
    __syncthreads();

    // ---- q gather ----
    if (outQ) {
        for (int i = tid; i < 64 * 16; i += NTHREADS) {
            int tt = i >> 4, c4 = i & 15;
            float4 v = *(const float4*)&cb[wix[tt] * DDIM + c4 * 4];
            *(float4*)&outQ[(long)(n0 + tt) * DDIM + c4 * 4] = v;
        }
    }
}

extern "C" void kernel_launch(void* const* d_in, const int* in_sizes, int n_in,
                              void* d_out, int out_size) {
    const float* h = (const float*)d_in[0];
    const float* cb = (const float*)d_in[1];
    float* out = (float*)d_out;

    float* outZ = nullptr;
    float* outQ = nullptr;
    if (out_size >= NTOK + NTOK * DDIM) { outZ = out; outQ = out + NTOK; }
    else if (out_size == NTOK * DDIM)   { outQ = out; }
    else                                { outZ = out; }

    cudaFuncSetAttribute(vq_main, cudaFuncAttributeMaxDynamicSharedMemorySize, SMEM_BYTES);
    vq_prep<<<4, 256>>>(cb);
    vq_main<<<NTOK / TM, NTHREADS, SMEM_BYTES>>>(h, cb, outZ, outQ);
}

// round 17
// speedup vs baseline: 1.8368x; 1.8368x over previous
#include <cuda_runtime.h>
#include <cstdint>

#define DDIM 64
#define KCODES 1024
#define NTOK 131072
#define TM 128
#define NTHREADS 512
#define PASSES 4
#define CPASS 256

typedef unsigned long long ull;

// ---------------- smem layout (bytes) ----------------
#define OFF_XF   0                    // float [64][128] = 32768 (d-major)
#define OFF_CS   32768                // 2 x float [64][256] = 131072 (double-buffered)
#define CS_STRIDE 65536
#define OFF_CN   163840               // float [1024] = 4096
#define OFF_XNS  167936               // float [128]
#define OFF_WIX  168448               // int [128]
#define SMEM_BYTES 168960
// reduction overlays Cs after the last pass:
#define OFF_REDV OFF_CS               // float [16][128] = 8192
#define OFF_REDI (OFF_CS + 8192)      // int   [16][128] = 8192

__device__ float g_cn[KCODES];                        // ||c||^2 (sequential, ref order)
__device__ __align__(16) float g_cbT[DDIM * KCODES];  // transposed codebook [d][k]

__global__ void vq_prep(const float* __restrict__ cb) {
    int k = blockIdx.x * blockDim.x + threadIdx.x;
    if (k >= KCODES) return;
    float acc = 0.f;
#pragma unroll
    for (int d = 0; d < DDIM; d++) {
        float c = cb[k * DDIM + d];
        acc = __fadd_rn(acc, __fmul_rn(c, c));
        g_cbT[d * KCODES + k] = c;
    }
    g_cn[k] = acc;
}

__device__ __forceinline__ uint32_t smem_u32(const void* p) {
    uint32_t a;
    asm("{ .reg .u64 t; cvta.to.shared.u64 t, %1; cvt.u32.u64 %0, t; }" : "=r"(a) : "l"(p));
    return a;
}
__device__ __forceinline__ uint4 lds128(uint32_t a) {
    uint4 v;
    asm volatile("ld.shared.v4.u32 {%0,%1,%2,%3}, [%4];"
                 : "=r"(v.x), "=r"(v.y), "=r"(v.z), "=r"(v.w) : "r"(a));
    return v;
}
__device__ __forceinline__ void lds2u64(ull& a0, ull& a1, uint32_t a) {
    asm volatile("ld.shared.v2.b64 {%0,%1}, [%2];" : "=l"(a0), "=l"(a1) : "r"(a));
}
__device__ __forceinline__ ull rep2(uint32_t x) {
    ull r;
    asm("mov.b64 %0, {%1,%1};" : "=l"(r) : "r"(x));
    return r;
}
__device__ __forceinline__ void fma2(ull& acc, ull x, ull c) {
    asm("fma.rn.f32x2 %0, %1, %2, %0;" : "+l"(acc) : "l"(x), "l"(c));
}

// async-fill one pass's code tile: Cs[buf][d][256] <- g_cbT[d][p*256 + col]
__device__ __forceinline__ void issue_cs(uint32_t sbase, int buf, int p) {
#pragma unroll
    for (int k = 0; k < 8; k++) {
        int i = threadIdx.x + k * NTHREADS;          // uint4 slot 0..4095
        int d = i >> 6;
        int col = (i & 63) << 2;
        uint32_t dst = sbase + OFF_CS + buf * CS_STRIDE + (uint32_t)((d * 256 + col) * 4);
        const char* src = (const char*)(g_cbT + d * KCODES + p * CPASS + col);
        asm volatile("cp.async.ca.shared.global [%0], [%1], 16;"
                     :: "r"(dst), "l"(src) : "memory");
    }
    asm volatile("cp.async.commit_group;" ::: "memory");
}

__global__ __launch_bounds__(NTHREADS, 1)
void vq_main(const float* __restrict__ h, const float* __restrict__ cb,
             float* __restrict__ outZ, float* __restrict__ outQ) {
    extern __shared__ char smem[];
    float* Xf  = (float*)(smem + OFF_XF);    // [64][128]
    float* Cn  = (float*)(smem + OFF_CN);
    float* xns = (float*)(smem + OFF_XNS);
    int*   wix = (int*)(smem + OFF_WIX);
    float* redv = (float*)(smem + OFF_REDV);
    int*   redi = (int*)(smem + OFF_REDI);
    const uint32_t sbase = smem_u32(smem);

    const int tid = threadIdx.x;
    const int wid = tid >> 5;
    const int l = tid & 31;
    const int n0 = blockIdx.x * TM;
    const int b = n0 >> 12;
    const long base = (long)b * 262144 + (n0 & 4095);

    // kick off pass-0 code tile immediately (overlaps the Xf gmem loads below)
    issue_cs(sbase, 0, 0);

    // ---- Xf [d][t]: coalesced LDG.128 -> STS.128, conflict-free ----
    for (int i = tid; i < 64 * 32; i += NTHREADS) {
        int d = i >> 5, t4 = i & 31;
        *(float4*)&Xf[d * 128 + t4 * 4] =
            *(const float4*)(h + base + (long)d * 4096 + t4 * 4);
    }
    for (int i = tid; i < KCODES; i += NTHREADS) Cn[i] = g_cn[i];
    __syncthreads();

    // ---- exact xn (sequential mul-then-add; bit-matches reference, R2-verified) ----
    if (tid < 128) {
        float acc = 0.f;
#pragma unroll
        for (int d = 0; d < 64; d++) {
            float xv = Xf[d * 128 + tid];
            acc = __fadd_rn(acc, __fmul_rn(xv, xv));
        }
        xns[tid] = acc;
    }
    __syncthreads();

    float xnr[4];
    {
        float4 v = *(const float4*)&xns[4 * l];
        xnr[0] = v.x; xnr[1] = v.y; xnr[2] = v.z; xnr[3] = v.w;
    }
    float best[4] = {3.4e38f, 3.4e38f, 3.4e38f, 3.4e38f};
    int bidx[4] = {0, 0, 0, 0};

    const uint32_t xaddr = sbase + OFF_XF + 16u * l;  // this thread's 4 tokens

#pragma unroll 1
    for (int p = 0; p < PASSES; p++) {
        // R13-verified order: wait for buf[p&1], BARRIER (separates pass p-1 reads
        // from the upcoming overwrite), THEN issue prefetch of pass p+1.
        asm volatile("cp.async.wait_group 0;" ::: "memory");
        __syncthreads();
        if (p + 1 < PASSES) issue_cs(sbase, (p + 1) & 1, p + 1);

        const uint32_t caddr = sbase + OFF_CS + (uint32_t)((p & 1) * CS_STRIDE) + 64u * wid;

        // acc[cp][t] = {s(k=2cp), s(k=2cp+1)} for token t (FFMA2 chain from 0 = R2-exact)
        ull acc[8][4];
#pragma unroll
        for (int cp = 0; cp < 8; cp++)
#pragma unroll
            for (int t = 0; t < 4; t++) acc[cp][t] = 0ull;

#pragma unroll 2
        for (int d = 0; d < 64; d++) {
            uint4 xv = lds128(xaddr + (uint32_t)(d * 512));
            ull x0 = rep2(xv.x), x1 = rep2(xv.y), x2 = rep2(xv.z), x3 = rep2(xv.w);
            uint32_t ca = caddr + (uint32_t)(d * 1024);
#pragma unroll
            for (int cq = 0; cq < 4; cq++) {
                ull c0, c1;                     // {c_k,c_k+1} natural pairs, warp-uniform
                lds2u64(c0, c1, ca + cq * 16);
                fma2(acc[cq * 2 + 0][0], x0, c0);
                fma2(acc[cq * 2 + 0][1], x1, c0);
                fma2(acc[cq * 2 + 0][2], x2, c0);
                fma2(acc[cq * 2 + 0][3], x3, c0);
                fma2(acc[cq * 2 + 1][0], x0, c1);
                fma2(acc[cq * 2 + 1][1], x1, c1);
                fma2(acc[cq * 2 + 1][2], x2, c1);
                fma2(acc[cq * 2 + 1][3], x3, c1);
            }
        }

        // epilogue: d2 = fl(fl(xn-2s)+cn), running argmin (ascending k, strict <)
        const int kw = p * CPASS + wid * 16;
#pragma unroll
        for (int cp = 0; cp < 8; cp++) {
            int k0 = kw + cp * 2;
            float cn0 = Cn[k0], cn1 = Cn[k0 + 1];
#pragma unroll
            for (int t = 0; t < 4; t++) {
                ull a = acc[cp][t];
                float slo = __uint_as_float((unsigned)(a & 0xffffffffull));
                float shi = __uint_as_float((unsigned)(a >> 32));
                float d2a = __fadd_rn(__fsub_rn(xnr[t], 2.0f * slo), cn0);
                float d2b = __fadd_rn(__fsub_rn(xnr[t], 2.0f * shi), cn1);
                if (d2a < best[t]) { best[t] = d2a; bidx[t] = k0; }
                if (d2b < best[t]) { best[t] = d2b; bidx[t] = k0 + 1; }
            }
        }
    }

    // ---- cross-warp reduce (lexicographic: value, then lowest k) ----
    __syncthreads();   // all passes done; safe to overlay Cs with reduction arrays
#pragma unroll
    for (int t = 0; t < 4; t++) {
        redv[wid * 128 + 4 * l + t] = best[t];
        redi[wid * 128 + 4 * l + t] = bidx[t];
    }
    __syncthreads();

    if (tid < 128) {
        float bv = redv[tid];
        int bi = redi[tid];
#pragma unroll
        for (int w = 1; w < 16; w++) {
            float v = redv[w * 128 + tid];
            int i2 = redi[w * 128 + tid];
            if (v < bv || (v == bv && i2 < bi)) { bv = v; bi = i2; }
        }
        wix[tid] = bi;
        if (outZ) outZ[n0 + tid] = (float)bi;
    }
    __syncthreads();

    // ---- q gather ----
    if (outQ) {
        for (int i = tid; i < 128 * 16; i += NTHREADS) {
            int tt = i >> 4, c4 = i & 15;
            float4 v = *(const float4*)&cb[wix[tt] * DDIM + c4 * 4];
            *(float4*)&outQ[(long)(n0 + tt) * DDIM + c4 * 4] = v;
        }
    }
}

extern "C" void kernel_launch(void* const* d_in, const int* in_sizes, int n_in,
                              void* d_out, int out_size) {
    const float* h = (const float*)d_in[0];
    const float* cb = (const float*)d_in[1];
    float* out = (float*)d_out;

    float* outZ = nullptr;
    float* outQ = nullptr;
    if (out_size >= NTOK + NTOK * DDIM) { outZ = out; outQ = out + NTOK; }
    else if (out_size == NTOK * DDIM)   { outQ = out; }
    else                                { outZ = out; }

    cudaFuncSetAttribute(vq_main, cudaFuncAttributeMaxDynamicSharedMemorySize, SMEM_BYTES);
    vq_prep<<<4, 256>>>(cb);
    vq_main<<<NTOK / TM, NTHREADS, SMEM_BYTES>>>(h, cb, outZ, outQ);
}